// round 8
// baseline (speedup 1.0000x reference)
#include <cuda_runtime.h>
#include <cuda_bf16.h>
#include <math.h>
#include <stdint.h>

// ---------------- problem constants ----------------
#define NGRAPH 128
#define NPER   20
#define NNODES 2560          // 128*20
#define EPG    380           // 20*19
#define NEDGE  48640         // 128*380
#define DIM    64
#define H1DIM  128
#define KK     8192          // H1DIM*DIM
#define KSPLIT 16            // k_fuse k-blocks (8 k each)

// ---------------- packed f32x2 helpers (sm_100+) ----------------
#define FMA2(acc, a, b) asm("fma.rn.f32x2 %0, %1, %2, %0;" : "+l"(acc) : "l"(a), "l"(b))
#define PACK2(out, f)   asm("mov.b64 %0, {%1, %1};" : "=l"(out) : "f"(f))
#define PACK2U(out, u)  asm("mov.b64 %0, {%1, %1};" : "=l"(out) : "r"(u))
#define UNPK2(lo, hi, p) asm("mov.b64 {%0, %1}, %2;" : "=f"(lo), "=f"(hi) : "l"(p))

// ---------------- scratch (static device globals; no allocation) ----------------
__device__ unsigned short g_h1b[NEDGE * H1DIM];   // 12.5 MB bf16 edge MLP hidden
__device__ float g_part[KSPLIT * NNODES * DIM];   // 10.5 MB split-K partials
__device__ float g_Gsum[NGRAPH * DIM];            // per-graph sum of out
__device__ float g_out[NNODES * DIM];
__device__ float g_h  [NNODES * DIM];

__device__ __forceinline__ float sigf(float x) { return 1.0f / (1.0f + expf(-x)); }

// ---------------- out = relu(x @ lin0_w + b); h = out ----------------
__global__ void k_lin0(const float* __restrict__ x, const float* __restrict__ w,
                       const float* __restrict__ b) {
    int idx = blockIdx.x * 256 + threadIdx.x;
    if (idx >= NNODES * DIM) return;
    int n = idx >> 6, o = idx & 63;
    const float* xr = x + n * 11;
    float acc = b[o];
#pragma unroll
    for (int f = 0; f < 11; f++) acc = fmaf(xr[f], w[f * 64 + o], acc);
    acc = fmaxf(acc, 0.0f);
    g_out[idx] = acc;
    g_h[idx]   = acc;
}

// ---------------- h1 = relu(edge_attr @ nn1_w + nn1_b) -> bf16 ----------------
__global__ void k_edge(const float* __restrict__ ea, const float* __restrict__ w,
                       const float* __restrict__ b) {
    int idx = blockIdx.x * 256 + threadIdx.x;
    if (idx >= NEDGE * H1DIM) return;
    int e = idx >> 7, k = idx & 127;
    const float* er = ea + e * 5;
    float acc = b[k];
#pragma unroll
    for (int f = 0; f < 5; f++) acc = fmaf(er[f], w[f * 128 + k], acc);
    acc = fmaxf(acc, 0.0f);
    g_h1b[idx] = __bfloat16_as_ushort(__float2bfloat16(acc));
}

// ---------------- per-graph sum of out (for Sx = Gsum - out[d]) ----------------
__global__ void k_gsum() {
    int g = blockIdx.x, o = threadIdx.x;    // 64 threads
    float s = 0.0f;
#pragma unroll
    for (int j = 0; j < NPER; j++) s += g_out[(g * NPER + j) * 64 + o];
    g_Gsum[g * 64 + o] = s;
}

// ---------------- fused agg: part[kb][d] = sum_{k in kb} M_k @ (A_g @ T_k) ----------------
// grid 2048 = 128 graphs x 16 k-blocks (8 k each); 128 threads.
// Stage1 (per 4-k round): warp kk computes C_k = A_g @ T_k (20x64).
// Stage2: all threads accumulate agg[d][cols] += sum_s h1[s->d,k] * C_k[s][cols].
// Column offset mapping C_OFF(c) = c + 4*(c>>5) kills og0/og4 bank conflicts.
__global__ void __launch_bounds__(128, 2) k_fuse(const float* __restrict__ nn2w) {
    extern __shared__ float dsm[];
    float* Us = dsm;                        // [4][64][68] fp32 T slices
    float* Cs = dsm + 17408;                // [4][20][68] fp32 C_k
    float* As = dsm + 17408 + 5440;         // [20][65]   fp32 A_g
    unsigned short* Hs = (unsigned short*)(As + 1300);   // [384][8] bf16 h1 slice

    int bx = blockIdx.x;
    int g = bx >> 4, kb = bx & 15;
    int t = threadIdx.x;
    int kk = t >> 5;                        // stage1: warp = k instance
    int sg = (t >> 3) & 3;                  // 4 s-groups of 5
    int og = t & 7;                         // 8 col-groups of 8 cols
    int oco = og * 8 + ((og >> 2) << 2);    // offset-mapped col base

    // stage A_g (padded rows of 65)
    for (int v = t; v < NPER * 64; v += 128) {
        int s = v >> 6, i = v & 63;
        As[s * 65 + i] = g_out[(g * NPER + s) * 64 + i];
    }
    // stage h1 slice: 380 edges x 8 bf16 (16B each)
    for (int e = t; e < EPG; e += 128)
        *(uint4*)(Hs + e * 8) = *(const uint4*)(g_h1b + (size_t)(g * EPG + e) * 128 + kb * 8);

    unsigned long long acc2a[4] = {0ULL, 0ULL, 0ULL, 0ULL};
    unsigned long long acc2b[4] = {0ULL, 0ULL, 0ULL, 0ULL};
    int dA = t >> 3;                        // 0..15
    int dB = 16 + (t >> 3);                 // t<32: 16..19

    for (int r = 0; r < 2; r++) {
        // stage Us: 4 consecutive T_k (64KB fp32), offset-mapped columns
        const float4* src = (const float4*)nn2w + ((size_t)(kb * 8 + r * 4) << 10);
        for (int v = t; v < 4096; v += 128) {
            int kv = v >> 10, rest = v & 1023;
            int i = rest >> 4, o4 = (rest & 15) << 2;
            *(float4*)(Us + kv * 4352 + i * 68 + o4 + ((o4 >> 5) << 2)) = src[v];
        }
        __syncthreads();

        // stage1: C_k = A_g @ T_k ; thread tile 5 s x 4 col-pairs
        {
            unsigned long long a1[5][4];
#pragma unroll
            for (int ss = 0; ss < 5; ss++)
#pragma unroll
                for (int c = 0; c < 4; c++) a1[ss][c] = 0ULL;
            const float* Uk = Us + kk * 4352 + oco;
            const float* Ab = As + (sg * 5) * 65;
#pragma unroll 4
            for (int i = 0; i < 64; i++) {
                ulonglong2 u0 = *(const ulonglong2*)(Uk + i * 68);
                ulonglong2 u1 = *(const ulonglong2*)(Uk + i * 68 + 4);
#pragma unroll
                for (int ss = 0; ss < 5; ss++) {
                    unsigned long long pa;
                    PACK2(pa, Ab[ss * 65 + i]);
                    FMA2(a1[ss][0], pa, u0.x);
                    FMA2(a1[ss][1], pa, u0.y);
                    FMA2(a1[ss][2], pa, u1.x);
                    FMA2(a1[ss][3], pa, u1.y);
                }
            }
#pragma unroll
            for (int ss = 0; ss < 5; ss++) {
                float* cd = Cs + kk * 1360 + (sg * 5 + ss) * 68 + oco;
                ulonglong2 v0, v1;
                v0.x = a1[ss][0]; v0.y = a1[ss][1];
                v1.x = a1[ss][2]; v1.y = a1[ss][3];
                *(ulonglong2*)cd = v0;
                *(ulonglong2*)(cd + 4) = v1;
            }
        }
        __syncthreads();

        // stage2: accumulate over this round's 4 k
#pragma unroll
        for (int kkk = 0; kkk < 4; kkk++) {
            int kidx = r * 4 + kkk;
            const float* CsK = Cs + kkk * 1360 + oco;
#pragma unroll 4
            for (int s = 0; s < NPER; s++) {
                {
                    int idx = (s * 19 + dA - (s < dA)) * 8 + kidx;
                    unsigned hv = Hs[idx];
                    unsigned fb = (s != dA) ? (hv << 16) : 0u;
                    unsigned long long pd;
                    PACK2U(pd, fb);
                    ulonglong2 c0 = *(const ulonglong2*)(CsK + s * 68);
                    ulonglong2 c1 = *(const ulonglong2*)(CsK + s * 68 + 4);
                    FMA2(acc2a[0], pd, c0.x); FMA2(acc2a[1], pd, c0.y);
                    FMA2(acc2a[2], pd, c1.x); FMA2(acc2a[3], pd, c1.y);
                }
                if (t < 32) {
                    int idx = (s * 19 + dB - (s < dB)) * 8 + kidx;
                    unsigned hv = Hs[idx];
                    unsigned fb = (s != dB) ? (hv << 16) : 0u;
                    unsigned long long pd;
                    PACK2U(pd, fb);
                    ulonglong2 c0 = *(const ulonglong2*)(CsK + s * 68);
                    ulonglong2 c1 = *(const ulonglong2*)(CsK + s * 68 + 4);
                    FMA2(acc2b[0], pd, c0.x); FMA2(acc2b[1], pd, c0.y);
                    FMA2(acc2b[2], pd, c1.x); FMA2(acc2b[3], pd, c1.y);
                }
            }
        }
        // __syncthreads() at next round's Us-staging protects Cs/Us reuse
    }

    // writeout (plain column order)
    {
        float v[8];
        UNPK2(v[0], v[1], acc2a[0]); UNPK2(v[2], v[3], acc2a[1]);
        UNPK2(v[4], v[5], acc2a[2]); UNPK2(v[6], v[7], acc2a[3]);
        float* gp = g_part + ((size_t)kb * NNODES + g * NPER + dA) * 64 + og * 8;
        *(float4*)gp       = make_float4(v[0], v[1], v[2], v[3]);
        *(float4*)(gp + 4) = make_float4(v[4], v[5], v[6], v[7]);
    }
    if (t < 32) {
        float v[8];
        UNPK2(v[0], v[1], acc2b[0]); UNPK2(v[2], v[3], acc2b[1]);
        UNPK2(v[4], v[5], acc2b[2]); UNPK2(v[6], v[7], acc2b[3]);
        float* gp = g_part + ((size_t)kb * NNODES + g * NPER + dB) * 64 + og * 8;
        *(float4*)gp       = make_float4(v[0], v[1], v[2], v[3]);
        *(float4*)(gp + 4) = make_float4(v[4], v[5], v[6], v[7]);
    }
}

// ---------------- fused per-node: m = relu(agg/19 + out@rootw + b); GRU -> h,out ----------------
__global__ void k_node(const float* __restrict__ nn2b, const float* __restrict__ rootw,
                       const float* __restrict__ convb,
                       const float* __restrict__ wih, const float* __restrict__ whh,
                       const float* __restrict__ bih, const float* __restrict__ bhh) {
    __shared__ float sx_s[4][64], out_s[4][64], h_s[4][64], m_s[4][64];
    __shared__ float g1[4][128], g2[4][64], g3[4][64];
    int t = threadIdx.x;
    int ln = t >> 6, o = t & 63;
    int n = blockIdx.x * 4 + ln;

    float outv = g_out[n * 64 + o];
    sx_s[ln][o]  = g_Gsum[(n / NPER) * 64 + o] - outv;
    out_s[ln][o] = outv;
    h_s[ln][o]   = g_h[n * 64 + o];
    __syncthreads();

    {
        float s = 0.0f;
#pragma unroll
        for (int q = 0; q < KSPLIT; q++) s += g_part[(size_t)q * (NNODES * DIM) + n * 64 + o];
        float acc = 0.0f;
#pragma unroll
        for (int i = 0; i < 64; i++) {
            s   = fmaf(sx_s[ln][i],  nn2b[i * 64 + o], s);
            acc = fmaf(out_s[ln][i], rootw[i * 64 + o], acc);
        }
        m_s[ln][o] = fmaxf(s * (1.0f / 19.0f) + acc + convb[o], 0.0f);
    }
    __syncthreads();

#pragma unroll
    for (int q = 0; q < 3; q++) {
        int j = o + q * 64;
        const float4* wi = (const float4*)(wih + j * 64);
        const float4* wh = (const float4*)(whh + j * 64);
        const float4* mr = (const float4*)(m_s[ln]);
        const float4* hr = (const float4*)(h_s[ln]);
        float gi = bih[j], gh = bhh[j];
#pragma unroll
        for (int qq = 0; qq < 16; qq++) {
            float4 a = mr[qq], b = wi[qq];
            gi = fmaf(a.x, b.x, fmaf(a.y, b.y, fmaf(a.z, b.z, fmaf(a.w, b.w, gi))));
            float4 c = hr[qq], d = wh[qq];
            gh = fmaf(c.x, d.x, fmaf(c.y, d.y, fmaf(c.z, d.z, fmaf(c.w, d.w, gh))));
        }
        if (q < 2) g1[ln][j] = gi + gh;
        else { g2[ln][o] = gi; g3[ln][o] = gh; }
    }
    __syncthreads();

    {
        float r  = sigf(g1[ln][o]);
        float z  = sigf(g1[ln][64 + o]);
        float nn = tanhf(g2[ln][o] + r * g3[ln][o]);
        float h  = (1.0f - z) * nn + z * h_s[ln][o];
        g_h[n * 64 + o]   = h;
        g_out[n * 64 + o] = h;
    }
}

// ---------------- Set2Set (3 steps) + final MLP head, one block per graph ----------------
__global__ void k_s2s(const float* __restrict__ wih, const float* __restrict__ whh,
                      const float* __restrict__ bih, const float* __restrict__ bhh,
                      const float* __restrict__ l1w, const float* __restrict__ l1b,
                      const float* __restrict__ l2w, const float* __restrict__ l2b,
                      float* __restrict__ outp) {
    __shared__ float og[NPER * 64];
    __shared__ float qs[128], hl[64], cl[64], gates[256], ev[NPER], av[NPER], red[64];
    __shared__ float ssum;
    int g = blockIdx.x, t = threadIdx.x;               // 128 threads

    for (int u = t; u < NPER * 64; u += 128) og[u] = g_out[g * NPER * 64 + u];
    qs[t] = 0.0f;
    if (t < 64) { hl[t] = 0.0f; cl[t] = 0.0f; }
    __syncthreads();

    for (int step = 0; step < 3; step++) {
        for (int j = t; j < 256; j += 128) {
            float acc = bih[j] + bhh[j];
            const float* wr = wih + j * 128;
            for (int i = 0; i < 128; i++) acc = fmaf(qs[i], wr[i], acc);
            const float* w2 = whh + j * 64;
            for (int i = 0; i < 64; i++) acc = fmaf(hl[i], w2[i], acc);
            gates[j] = acc;
        }
        __syncthreads();
        if (t < 64) {
            float ig = gates[t], fg = gates[64 + t], gg = gates[128 + t], og_ = gates[192 + t];
            float c = sigf(fg) * cl[t] + sigf(ig) * tanhf(gg);
            cl[t] = c;
            hl[t] = sigf(og_) * tanhf(c);
        }
        __syncthreads();
        if (t < NPER) {
            float acc = 0.0f;
            for (int o = 0; o < 64; o++) acc = fmaf(og[t * 64 + o], hl[o], acc);
            ev[t] = acc;
        }
        __syncthreads();
        if (t == 0) {
            float mx = ev[0];
            for (int v = 1; v < NPER; v++) mx = fmaxf(mx, ev[v]);
            float s = 0.0f;
            for (int v = 0; v < NPER; v++) { av[v] = expf(ev[v] - mx); s += av[v]; }
            ssum = s;
        }
        __syncthreads();
        if (t < 64) {
            float acc = 0.0f;
            for (int v = 0; v < NPER; v++) acc = fmaf(av[v], og[v * 64 + t], acc);
            qs[t] = hl[t];
            qs[64 + t] = acc / ssum;
        }
        __syncthreads();
    }

    if (t < 64) {
        float acc = l1b[t];
        for (int i = 0; i < 128; i++) acc = fmaf(qs[i], l1w[i * 64 + t], acc);
        acc = fmaxf(acc, 0.0f);
        red[t] = acc * l2w[t];
    }
    __syncthreads();
    if (t == 0) {
        float y = l2b[0];
        for (int o = 0; o < 64; o++) y += red[o];
        outp[g] = y;
    }
}

// ---------------- host launch ----------------
extern "C" void kernel_launch(void* const* d_in, const int* in_sizes, int n_in,
                              void* d_out, int out_size) {
    const float* x       = (const float*)d_in[0];
    const float* ea      = (const float*)d_in[2];
    const float* lin0_w  = (const float*)d_in[4];
    const float* lin0_b  = (const float*)d_in[5];
    const float* nn1_w   = (const float*)d_in[6];
    const float* nn1_b   = (const float*)d_in[7];
    const float* nn2_w   = (const float*)d_in[8];
    const float* nn2_b   = (const float*)d_in[9];
    const float* root_w  = (const float*)d_in[10];
    const float* conv_b  = (const float*)d_in[11];
    const float* gru_wih = (const float*)d_in[12];
    const float* gru_whh = (const float*)d_in[13];
    const float* gru_bih = (const float*)d_in[14];
    const float* gru_bhh = (const float*)d_in[15];
    const float* lstm_wih = (const float*)d_in[16];
    const float* lstm_whh = (const float*)d_in[17];
    const float* lstm_bih = (const float*)d_in[18];
    const float* lstm_bhh = (const float*)d_in[19];
    const float* lin1_w  = (const float*)d_in[20];
    const float* lin1_b  = (const float*)d_in[21];
    const float* lin2_w  = (const float*)d_in[22];
    const float* lin2_b  = (const float*)d_in[23];
    float* outp = (float*)d_out;

    const int fuseSmem = 102736;   // Us 69632 + Cs 21760 + As 5200 + Hs 6144
    cudaFuncSetAttribute(k_fuse, cudaFuncAttributeMaxDynamicSharedMemorySize, fuseSmem);

    k_lin0<<<(NNODES * DIM + 255) / 256, 256>>>(x, lin0_w, lin0_b);
    k_edge<<<(NEDGE * H1DIM) / 256, 256>>>(ea, nn1_w, nn1_b);

    for (int it = 0; it < 3; it++) {
        k_fuse<<<NGRAPH * KSPLIT, 128, fuseSmem>>>(nn2_w);
        k_gsum<<<NGRAPH, 64>>>();
        k_node<<<NNODES / 4, 256>>>(nn2_b, root_w, conv_b,
                                    gru_wih, gru_whh, gru_bih, gru_bhh);
    }

    k_s2s<<<NGRAPH, 128>>>(lstm_wih, lstm_whh, lstm_bih, lstm_bhh,
                           lin1_w, lin1_b, lin2_w, lin2_b, outp);
}

// round 9
// speedup vs baseline: 1.2016x; 1.2016x over previous
#include <cuda_runtime.h>
#include <cuda_bf16.h>
#include <math.h>
#include <stdint.h>

// ---------------- problem constants ----------------
#define NGRAPH 128
#define NPER   20
#define NNODES 2560          // 128*20
#define EPG    380           // 20*19
#define NEDGE  48640         // 128*380
#define DIM    64
#define H1DIM  128
#define KK     8192          // H1DIM*DIM
#define KSPLIT 32            // k_agg K-splits (each CTA covers 256 k)

// ---------------- packed f32x2 helpers (sm_100+) ----------------
#define FMA2(acc, a, b) asm("fma.rn.f32x2 %0, %1, %2, %0;" : "+l"(acc) : "l"(a), "l"(b))
#define PACK2(out, f)   asm("mov.b64 %0, {%1, %1};" : "=l"(out) : "f"(f))
#define PACK2U(out, u)  asm("mov.b64 %0, {%1, %1};" : "=l"(out) : "r"(u))
#define UNPK2(lo, hi, p) asm("mov.b64 {%0, %1}, %2;" : "=f"(lo), "=f"(hi) : "l"(p))
#define CVTB2(out, lo, hi) asm("cvt.rn.bf16x2.f32 %0, %1, %2;" : "=r"(out) : "f"(hi), "f"(lo))

// ---------------- scratch (static device globals; no allocation) ----------------
__device__ unsigned short g_h1b[NEDGE * H1DIM];   // 12.5 MB bf16 edge MLP hidden
__device__ unsigned short g_Pb[NNODES * KK];      // 42 MB bf16 outer-product accumulators
__device__ float g_part[KSPLIT * NNODES * DIM];   // 21 MB split-K partials
__device__ float g_Sx[NNODES * DIM];
__device__ float g_out[NNODES * DIM];
__device__ float g_h  [NNODES * DIM];

__device__ __forceinline__ float sigf(float x) { return 1.0f / (1.0f + expf(-x)); }

// ---------------- out = relu(x @ lin0_w + b); h = out ----------------
__global__ void k_lin0(const float* __restrict__ x, const float* __restrict__ w,
                       const float* __restrict__ b) {
    int idx = blockIdx.x * 256 + threadIdx.x;
    if (idx >= NNODES * DIM) return;
    int n = idx >> 6, o = idx & 63;
    const float* xr = x + n * 11;
    float acc = b[o];
#pragma unroll
    for (int f = 0; f < 11; f++) acc = fmaf(xr[f], w[f * 64 + o], acc);
    acc = fmaxf(acc, 0.0f);
    g_out[idx] = acc;
    g_h[idx]   = acc;
}

// ---------------- h1 = relu(edge_attr @ nn1_w + nn1_b) -> bf16 ----------------
__global__ void k_edge(const float* __restrict__ ea, const float* __restrict__ w,
                       const float* __restrict__ b) {
    int idx = blockIdx.x * 256 + threadIdx.x;
    if (idx >= NEDGE * H1DIM) return;
    int e = idx >> 7, k = idx & 127;
    const float* er = ea + e * 5;
    float acc = b[k];
#pragma unroll
    for (int f = 0; f < 5; f++) acc = fmaf(er[f], w[f * 128 + k], acc);
    acc = fmaxf(acc, 0.0f);
    g_h1b[idx] = __bfloat16_as_ushort(__float2bfloat16(acc));
}

// ---------------- P[d] = sum_s h1[s->d] (outer) out[s] -> bf16; also Sx[d] ----------------
__global__ void k_p() {
    __shared__ float xs[19 * 64];
    __shared__ unsigned hsu[19 * 64];   // bf16 pairs (2 k per u32)
    int n = blockIdx.x;
    int g = n / NPER, d = n % NPER;
    int t = threadIdx.x;                // 256 threads

    for (int u = t; u < 19 * 64; u += 256) {
        int sI = u >> 6, i = u & 63;
        int s = sI + (sI >= d);
        xs[u] = g_out[(g * NPER + s) * 64 + i];
    }
    for (int u = t; u < 19 * 64; u += 256) {
        int sI = u >> 6, kp = u & 63;
        int s = sI + (sI >= d);
        int j = (d < s) ? d : d - 1;
        hsu[u] = ((const unsigned*)g_h1b)[(size_t)(g * EPG + s * 19 + j) * 64 + kp];
    }
    __syncthreads();

    if (t < 64) {
        float acc = 0.0f;
#pragma unroll
        for (int sI = 0; sI < 19; sI++) acc += xs[sI * 64 + t];
        g_Sx[n * 64 + t] = acc;
    }

    int kg = t >> 3, ig = t & 7;        // 4 k-rows x 8 i-cols per thread
    unsigned long long a2[4][4];
#pragma unroll
    for (int r = 0; r < 4; r++)
#pragma unroll
        for (int c = 0; c < 4; c++) a2[r][c] = 0ULL;

    for (int sI = 0; sI < 19; sI++) {
        uint2 hh = *(const uint2*)(hsu + sI * 64 + (kg << 1));
        float f0 = __uint_as_float(hh.x << 16);
        float f1 = __uint_as_float(hh.x & 0xFFFF0000u);
        float f2 = __uint_as_float(hh.y << 16);
        float f3 = __uint_as_float(hh.y & 0xFFFF0000u);
        ulonglong2 xa = *(const ulonglong2*)(xs + sI * 64 + (ig << 3));
        ulonglong2 xb = *(const ulonglong2*)(xs + sI * 64 + (ig << 3) + 4);
        unsigned long long h0, h1p, h2, h3;
        PACK2(h0, f0); PACK2(h1p, f1); PACK2(h2, f2); PACK2(h3, f3);
        FMA2(a2[0][0], h0, xa.x);  FMA2(a2[0][1], h0, xa.y);
        FMA2(a2[0][2], h0, xb.x);  FMA2(a2[0][3], h0, xb.y);
        FMA2(a2[1][0], h1p, xa.x); FMA2(a2[1][1], h1p, xa.y);
        FMA2(a2[1][2], h1p, xb.x); FMA2(a2[1][3], h1p, xb.y);
        FMA2(a2[2][0], h2, xa.x);  FMA2(a2[2][1], h2, xa.y);
        FMA2(a2[2][2], h2, xb.x);  FMA2(a2[2][3], h2, xb.y);
        FMA2(a2[3][0], h3, xa.x);  FMA2(a2[3][1], h3, xa.y);
        FMA2(a2[3][2], h3, xb.x);  FMA2(a2[3][3], h3, xb.y);
    }

    unsigned short* pd = g_Pb + (size_t)n * KK;
#pragma unroll
    for (int r = 0; r < 4; r++) {
        int k = (kg << 2) + r;
        unsigned o0, o1, o2, o3;
        float lo, hi;
        UNPK2(lo, hi, a2[r][0]); CVTB2(o0, lo, hi);
        UNPK2(lo, hi, a2[r][1]); CVTB2(o1, lo, hi);
        UNPK2(lo, hi, a2[r][2]); CVTB2(o2, lo, hi);
        UNPK2(lo, hi, a2[r][3]); CVTB2(o3, lo, hi);
        *(uint4*)(pd + k * 64 + (ig << 3)) = make_uint4(o0, o1, o2, o3);
    }
}

// ---------------- k_agg: partial[ks] = Pb[128-row tile] @ T over 256-k slice ----------------
// grid 640 = 20 tiles x 32 K-splits; 256 threads; thread tile 4 rows x 8 cols.
// P read straight from global (warp broadcast), held in regs for 8 k; only T staged in smem.
__global__ void __launch_bounds__(256, 3) k_agg(const float* __restrict__ nn2w) {
    __shared__ float Ts[32 * 64];       // 8 KB fp32 T chunk
    int bx = blockIdx.x;
    int tile = bx >> 5, ks = bx & 31;
    int n0 = tile * 128;
    int kbase = ks * 256;
    int t = threadIdx.x;
    int tx = t & 7, ry = t >> 3;        // cols tx*8..+7, rows ry*4..+3
    int r0 = n0 + (ry << 2);

    unsigned long long acc[4][4];       // [row][col-pair] f32x2 {col even, col odd}
#pragma unroll
    for (int r = 0; r < 4; r++)
#pragma unroll
        for (int c = 0; c < 4; c++) acc[r][c] = 0ULL;

    for (int ch = 0; ch < 8; ch++) {
        int kb = kbase + (ch << 5);
        if (ch) __syncthreads();
        // stage T chunk: 32 k x 64 o fp32 (512 float4, 2 per thread)
#pragma unroll
        for (int j = 0; j < 2; j++) {
            int flat = t + j * 256;     // 0..511 float4
            int kk = flat >> 4, o4 = (flat & 15) << 2;
            *(float4*)(Ts + (kk << 6) + o4) =
                *(const float4*)(nn2w + (size_t)(kb + kk) * 64 + o4);
        }
        __syncthreads();
#pragma unroll
        for (int kq = 0; kq < 4; kq++) {
            // P: 4 rows x 8 k bf16, one LDG.128 per row (broadcast across 8 tx lanes)
            uint4 q[4];
#pragma unroll
            for (int r = 0; r < 4; r++)
                q[r] = *(const uint4*)(g_Pb + (size_t)(r0 + r) * KK + kb + (kq << 3));
#pragma unroll
            for (int kk = 0; kk < 8; kk++) {
                const ulonglong2* tp =
                    (const ulonglong2*)(Ts + (((kq << 3) + kk) << 6) + (tx << 3));
                ulonglong2 ta = tp[0], tb = tp[1];   // 4 natural f32x2 col-pairs
#pragma unroll
                for (int r = 0; r < 4; r++) {
                    unsigned w = ((const unsigned*)&q[r])[kk >> 1];
                    unsigned f = (kk & 1) ? (w & 0xFFFF0000u) : (w << 16);
                    unsigned long long pd;
                    PACK2U(pd, f);
                    FMA2(acc[r][0], pd, ta.x);
                    FMA2(acc[r][1], pd, ta.y);
                    FMA2(acc[r][2], pd, tb.x);
                    FMA2(acc[r][3], pd, tb.y);
                }
            }
        }
    }

    float* gp = g_part + (size_t)ks * (NNODES * DIM) + (size_t)r0 * 64 + (tx << 3);
#pragma unroll
    for (int r = 0; r < 4; r++) {
        ulonglong2 v0, v1;
        v0.x = acc[r][0]; v0.y = acc[r][1];
        v1.x = acc[r][2]; v1.y = acc[r][3];
        *(ulonglong2*)(gp + (size_t)r * 64)     = v0;
        *(ulonglong2*)(gp + (size_t)r * 64 + 4) = v1;
    }
}

// ---------------- fused per-node: m = relu(agg/19 + out@rootw + b); GRU -> h,out ----------------
__global__ void k_node(const float* __restrict__ nn2b, const float* __restrict__ rootw,
                       const float* __restrict__ convb,
                       const float* __restrict__ wih, const float* __restrict__ whh,
                       const float* __restrict__ bih, const float* __restrict__ bhh) {
    __shared__ float sx_s[4][64], out_s[4][64], h_s[4][64], m_s[4][64];
    __shared__ float g1[4][128], g2[4][64], g3[4][64];
    int t = threadIdx.x;
    int ln = t >> 6, o = t & 63;
    int n = blockIdx.x * 4 + ln;

    sx_s[ln][o]  = g_Sx[n * 64 + o];
    out_s[ln][o] = g_out[n * 64 + o];
    h_s[ln][o]   = g_h[n * 64 + o];
    __syncthreads();

    {
        float s = 0.0f;
#pragma unroll
        for (int q = 0; q < KSPLIT; q++) s += g_part[(size_t)q * (NNODES * DIM) + n * 64 + o];
        float acc = 0.0f;
#pragma unroll
        for (int i = 0; i < 64; i++) {
            s   = fmaf(sx_s[ln][i],  nn2b[i * 64 + o], s);
            acc = fmaf(out_s[ln][i], rootw[i * 64 + o], acc);
        }
        m_s[ln][o] = fmaxf(s * (1.0f / 19.0f) + acc + convb[o], 0.0f);
    }
    __syncthreads();

#pragma unroll
    for (int q = 0; q < 3; q++) {
        int j = o + q * 64;
        const float4* wi = (const float4*)(wih + j * 64);
        const float4* wh = (const float4*)(whh + j * 64);
        const float4* mr = (const float4*)(m_s[ln]);
        const float4* hr = (const float4*)(h_s[ln]);
        float gi = bih[j], gh = bhh[j];
#pragma unroll
        for (int qq = 0; qq < 16; qq++) {
            float4 a = mr[qq], b = wi[qq];
            gi = fmaf(a.x, b.x, fmaf(a.y, b.y, fmaf(a.z, b.z, fmaf(a.w, b.w, gi))));
            float4 c = hr[qq], d = wh[qq];
            gh = fmaf(c.x, d.x, fmaf(c.y, d.y, fmaf(c.z, d.z, fmaf(c.w, d.w, gh))));
        }
        if (q < 2) g1[ln][j] = gi + gh;
        else { g2[ln][o] = gi; g3[ln][o] = gh; }
    }
    __syncthreads();

    {
        float r  = sigf(g1[ln][o]);
        float z  = sigf(g1[ln][64 + o]);
        float nn = tanhf(g2[ln][o] + r * g3[ln][o]);
        float h  = (1.0f - z) * nn + z * h_s[ln][o];
        g_h[n * 64 + o]   = h;
        g_out[n * 64 + o] = h;
    }
}

// ---------------- Set2Set (3 steps) + final MLP head, one block per graph ----------------
__global__ void k_s2s(const float* __restrict__ wih, const float* __restrict__ whh,
                      const float* __restrict__ bih, const float* __restrict__ bhh,
                      const float* __restrict__ l1w, const float* __restrict__ l1b,
                      const float* __restrict__ l2w, const float* __restrict__ l2b,
                      float* __restrict__ outp) {
    __shared__ float og[NPER * 64];
    __shared__ float qs[128], hl[64], cl[64], gates[256], ev[NPER], av[NPER], red[64];
    __shared__ float ssum;
    int g = blockIdx.x, t = threadIdx.x;               // 128 threads

    for (int u = t; u < NPER * 64; u += 128) og[u] = g_out[g * NPER * 64 + u];
    qs[t] = 0.0f;
    if (t < 64) { hl[t] = 0.0f; cl[t] = 0.0f; }
    __syncthreads();

    for (int step = 0; step < 3; step++) {
        for (int j = t; j < 256; j += 128) {
            float acc = bih[j] + bhh[j];
            const float* wr = wih + j * 128;
            for (int i = 0; i < 128; i++) acc = fmaf(qs[i], wr[i], acc);
            const float* w2 = whh + j * 64;
            for (int i = 0; i < 64; i++) acc = fmaf(hl[i], w2[i], acc);
            gates[j] = acc;
        }
        __syncthreads();
        if (t < 64) {
            float ig = gates[t], fg = gates[64 + t], gg = gates[128 + t], og_ = gates[192 + t];
            float c = sigf(fg) * cl[t] + sigf(ig) * tanhf(gg);
            cl[t] = c;
            hl[t] = sigf(og_) * tanhf(c);
        }
        __syncthreads();
        if (t < NPER) {
            float acc = 0.0f;
            for (int o = 0; o < 64; o++) acc = fmaf(og[t * 64 + o], hl[o], acc);
            ev[t] = acc;
        }
        __syncthreads();
        if (t == 0) {
            float mx = ev[0];
            for (int v = 1; v < NPER; v++) mx = fmaxf(mx, ev[v]);
            float s = 0.0f;
            for (int v = 0; v < NPER; v++) { av[v] = expf(ev[v] - mx); s += av[v]; }
            ssum = s;
        }
        __syncthreads();
        if (t < 64) {
            float acc = 0.0f;
            for (int v = 0; v < NPER; v++) acc = fmaf(av[v], og[v * 64 + t], acc);
            qs[t] = hl[t];
            qs[64 + t] = acc / ssum;
        }
        __syncthreads();
    }

    if (t < 64) {
        float acc = l1b[t];
        for (int i = 0; i < 128; i++) acc = fmaf(qs[i], l1w[i * 64 + t], acc);
        acc = fmaxf(acc, 0.0f);
        red[t] = acc * l2w[t];
    }
    __syncthreads();
    if (t == 0) {
        float y = l2b[0];
        for (int o = 0; o < 64; o++) y += red[o];
        outp[g] = y;
    }
}

// ---------------- host launch ----------------
extern "C" void kernel_launch(void* const* d_in, const int* in_sizes, int n_in,
                              void* d_out, int out_size) {
    const float* x       = (const float*)d_in[0];
    const float* ea      = (const float*)d_in[2];
    const float* lin0_w  = (const float*)d_in[4];
    const float* lin0_b  = (const float*)d_in[5];
    const float* nn1_w   = (const float*)d_in[6];
    const float* nn1_b   = (const float*)d_in[7];
    const float* nn2_w   = (const float*)d_in[8];
    const float* nn2_b   = (const float*)d_in[9];
    const float* root_w  = (const float*)d_in[10];
    const float* conv_b  = (const float*)d_in[11];
    const float* gru_wih = (const float*)d_in[12];
    const float* gru_whh = (const float*)d_in[13];
    const float* gru_bih = (const float*)d_in[14];
    const float* gru_bhh = (const float*)d_in[15];
    const float* lstm_wih = (const float*)d_in[16];
    const float* lstm_whh = (const float*)d_in[17];
    const float* lstm_bih = (const float*)d_in[18];
    const float* lstm_bhh = (const float*)d_in[19];
    const float* lin1_w  = (const float*)d_in[20];
    const float* lin1_b  = (const float*)d_in[21];
    const float* lin2_w  = (const float*)d_in[22];
    const float* lin2_b  = (const float*)d_in[23];
    float* outp = (float*)d_out;

    k_lin0<<<(NNODES * DIM + 255) / 256, 256>>>(x, lin0_w, lin0_b);
    k_edge<<<(NEDGE * H1DIM) / 256, 256>>>(ea, nn1_w, nn1_b);

    for (int it = 0; it < 3; it++) {
        k_p<<<NNODES, 256>>>();
        k_agg<<<640, 256>>>(nn2_w);
        k_node<<<NNODES / 4, 256>>>(nn2_b, root_w, conv_b,
                                    gru_wih, gru_whh, gru_bih, gru_bhh);
    }

    k_s2s<<<NGRAPH, 128>>>(lstm_wih, lstm_whh, lstm_bih, lstm_bhh,
                           lin1_w, lin1_b, lin2_w, lin2_b, outp);
}

// round 10
// speedup vs baseline: 1.4025x; 1.1672x over previous
#include <cuda_runtime.h>
#include <cuda_bf16.h>
#include <math.h>
#include <stdint.h>

// ---------------- problem constants ----------------
#define NGRAPH 128
#define NPER   20
#define NNODES 2560          // 128*20
#define EPG    380           // 20*19
#define NEDGE  48640         // 128*380
#define DIM    64
#define H1DIM  128
#define KK     8192          // H1DIM*DIM
#define KSPLIT 32            // k_agg K-splits (each CTA covers 256 k)

// ---------------- packed f32x2 helpers (sm_100+) ----------------
#define FMA2(acc, a, b) asm("fma.rn.f32x2 %0, %1, %2, %0;" : "+l"(acc) : "l"(a), "l"(b))
#define PACK2(out, f)   asm("mov.b64 %0, {%1, %1};" : "=l"(out) : "f"(f))
#define PACK2U(out, u)  asm("mov.b64 %0, {%1, %1};" : "=l"(out) : "r"(u))
#define PACK2UU(out, a, b) asm("mov.b64 %0, {%1, %2};" : "=l"(out) : "r"(a), "r"(b))
#define UNPK2(lo, hi, p) asm("mov.b64 {%0, %1}, %2;" : "=f"(lo), "=f"(hi) : "l"(p))
#define CVTB2(out, lo, hi) asm("cvt.rn.bf16x2.f32 %0, %1, %2;" : "=r"(out) : "f"(hi), "f"(lo))

// ---------------- scratch (static device globals; no allocation) ----------------
__device__ unsigned short g_h1b[NEDGE * H1DIM];   // 12.5 MB bf16 edge MLP hidden
__device__ unsigned short g_Pb[NNODES * KK];      // 42 MB bf16 outer-product accumulators
__device__ float g_part[KSPLIT * NNODES * DIM];   // 21 MB split-K partials
__device__ float g_Sx[NNODES * DIM];
__device__ float g_out[NNODES * DIM];
__device__ float g_h  [NNODES * DIM];

__device__ __forceinline__ float sigf(float x) { return 1.0f / (1.0f + expf(-x)); }

// ---------------- out = relu(x @ lin0_w + b); h = out ----------------
__global__ void k_lin0(const float* __restrict__ x, const float* __restrict__ w,
                       const float* __restrict__ b) {
    int idx = blockIdx.x * 256 + threadIdx.x;
    if (idx >= NNODES * DIM) return;
    int n = idx >> 6, o = idx & 63;
    const float* xr = x + n * 11;
    float acc = b[o];
#pragma unroll
    for (int f = 0; f < 11; f++) acc = fmaf(xr[f], w[f * 64 + o], acc);
    acc = fmaxf(acc, 0.0f);
    g_out[idx] = acc;
    g_h[idx]   = acc;
}

// ---------------- h1 = relu(edge_attr @ nn1_w + nn1_b) -> bf16 ----------------
__global__ void k_edge(const float* __restrict__ ea, const float* __restrict__ w,
                       const float* __restrict__ b) {
    int idx = blockIdx.x * 256 + threadIdx.x;
    if (idx >= NEDGE * H1DIM) return;
    int e = idx >> 7, k = idx & 127;
    const float* er = ea + e * 5;
    float acc = b[k];
#pragma unroll
    for (int f = 0; f < 5; f++) acc = fmaf(er[f], w[f * 128 + k], acc);
    acc = fmaxf(acc, 0.0f);
    g_h1b[idx] = __bfloat16_as_ushort(__float2bfloat16(acc));
}

// ---------------- P[d] = sum_s h1[s->d] (outer) out[s] -> bf16; also Sx[d] ----------------
__global__ void k_p() {
    __shared__ float xs[19 * 64];
    __shared__ unsigned hsu[19 * 64];   // bf16 pairs (2 k per u32)
    int n = blockIdx.x;
    int g = n / NPER, d = n % NPER;
    int t = threadIdx.x;                // 256 threads

    for (int u = t; u < 19 * 64; u += 256) {
        int sI = u >> 6, i = u & 63;
        int s = sI + (sI >= d);
        xs[u] = g_out[(g * NPER + s) * 64 + i];
    }
    for (int u = t; u < 19 * 64; u += 256) {
        int sI = u >> 6, kp = u & 63;
        int s = sI + (sI >= d);
        int j = (d < s) ? d : d - 1;
        hsu[u] = ((const unsigned*)g_h1b)[(size_t)(g * EPG + s * 19 + j) * 64 + kp];
    }
    __syncthreads();

    if (t < 64) {
        float acc = 0.0f;
#pragma unroll
        for (int sI = 0; sI < 19; sI++) acc += xs[sI * 64 + t];
        g_Sx[n * 64 + t] = acc;
    }

    int kg = t >> 3, ig = t & 7;        // 4 k-rows x 8 i-cols per thread
    unsigned long long a2[4][4];
#pragma unroll
    for (int r = 0; r < 4; r++)
#pragma unroll
        for (int c = 0; c < 4; c++) a2[r][c] = 0ULL;

    for (int sI = 0; sI < 19; sI++) {
        uint2 hh = *(const uint2*)(hsu + sI * 64 + (kg << 1));
        float f0 = __uint_as_float(hh.x << 16);
        float f1 = __uint_as_float(hh.x & 0xFFFF0000u);
        float f2 = __uint_as_float(hh.y << 16);
        float f3 = __uint_as_float(hh.y & 0xFFFF0000u);
        ulonglong2 xa = *(const ulonglong2*)(xs + sI * 64 + (ig << 3));
        ulonglong2 xb = *(const ulonglong2*)(xs + sI * 64 + (ig << 3) + 4);
        unsigned long long h0, h1p, h2, h3;
        PACK2(h0, f0); PACK2(h1p, f1); PACK2(h2, f2); PACK2(h3, f3);
        FMA2(a2[0][0], h0, xa.x);  FMA2(a2[0][1], h0, xa.y);
        FMA2(a2[0][2], h0, xb.x);  FMA2(a2[0][3], h0, xb.y);
        FMA2(a2[1][0], h1p, xa.x); FMA2(a2[1][1], h1p, xa.y);
        FMA2(a2[1][2], h1p, xb.x); FMA2(a2[1][3], h1p, xb.y);
        FMA2(a2[2][0], h2, xa.x);  FMA2(a2[2][1], h2, xa.y);
        FMA2(a2[2][2], h2, xb.x);  FMA2(a2[2][3], h2, xb.y);
        FMA2(a2[3][0], h3, xa.x);  FMA2(a2[3][1], h3, xa.y);
        FMA2(a2[3][2], h3, xb.x);  FMA2(a2[3][3], h3, xb.y);
    }

    unsigned short* pd = g_Pb + (size_t)n * KK;
#pragma unroll
    for (int r = 0; r < 4; r++) {
        int k = (kg << 2) + r;
        unsigned o0, o1, o2, o3;
        float lo, hi;
        UNPK2(lo, hi, a2[r][0]); CVTB2(o0, lo, hi);
        UNPK2(lo, hi, a2[r][1]); CVTB2(o1, lo, hi);
        UNPK2(lo, hi, a2[r][2]); CVTB2(o2, lo, hi);
        UNPK2(lo, hi, a2[r][3]); CVTB2(o3, lo, hi);
        *(uint4*)(pd + k * 64 + (ig << 3)) = make_uint4(o0, o1, o2, o3);
    }
}

// ---------------- k_agg: partial[ks] = Pb[128-row tile] @ T over 256-k slice ----------------
// grid 640 = 20 tiles x 32 K-splits; 128 threads; thread tile 8 rows x 8 cols.
// P from global (warp broadcast, regs for 8 k); T staged in smem as bf16 pairs:
// one LDS.128 per k fetches all 8 cols; expansion to f32x2 runs on the alu pipe.
__global__ void __launch_bounds__(128, 4) k_agg(const float* __restrict__ nn2w) {
    __shared__ unsigned Tsu[32 * 32];   // 4 KB: [k][col-pair] bf16x2
    int bx = blockIdx.x;
    int tile = bx >> 5, ks = bx & 31;
    int n0 = tile * 128;
    int kbase = ks * 256;
    int t = threadIdx.x;
    int tx = t & 7, ry = t >> 3;        // cols tx*8..+7, rows ry*8..+7
    int r0 = n0 + (ry << 3);

    unsigned long long acc[8][4];       // [row][col-pair] f32x2 {col even, col odd}
#pragma unroll
    for (int r = 0; r < 8; r++)
#pragma unroll
        for (int c = 0; c < 4; c++) acc[r][c] = 0ULL;

    for (int ch = 0; ch < 8; ch++) {
        int kb = kbase + (ch << 5);
        if (ch) __syncthreads();
        // stage T chunk: 32 k x 64 o fp32 -> bf16 pairs (512 float4 -> 512 uint2)
#pragma unroll
        for (int j = 0; j < 4; j++) {
            int flat = t + j * 128;     // 0..511
            int kk = flat >> 4, o4 = (flat & 15) << 2;
            float4 v = *(const float4*)(nn2w + (size_t)(kb + kk) * 64 + o4);
            unsigned u0, u1;
            CVTB2(u0, v.x, v.y);
            CVTB2(u1, v.z, v.w);
            *(uint2*)(Tsu + (kk << 5) + (o4 >> 1)) = make_uint2(u0, u1);
        }
        __syncthreads();
#pragma unroll
        for (int kq = 0; kq < 4; kq++) {
            // P: 8 rows x 8 k bf16, one LDG.128 per row (broadcast across 8 tx lanes)
            uint4 q[8];
#pragma unroll
            for (int r = 0; r < 8; r++)
                q[r] = *(const uint4*)(g_Pb + (size_t)(r0 + r) * KK + kb + (kq << 3));
#pragma unroll
            for (int kk = 0; kk < 8; kk++) {
                // one LDS.128: 4 bf16x2 pairs = this thread's 8 T cols for k
                uint4 tw = *(const uint4*)(Tsu + (((kq << 3) + kk) << 5) + (tx << 2));
                unsigned long long tp0, tp1, tp2, tp3;
                PACK2UU(tp0, tw.x << 16, tw.x & 0xFFFF0000u);
                PACK2UU(tp1, tw.y << 16, tw.y & 0xFFFF0000u);
                PACK2UU(tp2, tw.z << 16, tw.z & 0xFFFF0000u);
                PACK2UU(tp3, tw.w << 16, tw.w & 0xFFFF0000u);
#pragma unroll
                for (int r = 0; r < 8; r++) {
                    unsigned w = ((const unsigned*)&q[r])[kk >> 1];
                    unsigned f = (kk & 1) ? (w & 0xFFFF0000u) : (w << 16);
                    unsigned long long pd;
                    PACK2U(pd, f);
                    FMA2(acc[r][0], pd, tp0);
                    FMA2(acc[r][1], pd, tp1);
                    FMA2(acc[r][2], pd, tp2);
                    FMA2(acc[r][3], pd, tp3);
                }
            }
        }
    }

    float* gp = g_part + (size_t)ks * (NNODES * DIM) + (size_t)r0 * 64 + (tx << 3);
#pragma unroll
    for (int r = 0; r < 8; r++) {
        ulonglong2 v0, v1;
        v0.x = acc[r][0]; v0.y = acc[r][1];
        v1.x = acc[r][2]; v1.y = acc[r][3];
        *(ulonglong2*)(gp + (size_t)r * 64)     = v0;
        *(ulonglong2*)(gp + (size_t)r * 64 + 4) = v1;
    }
}

// ---------------- fused per-node: m = relu(agg/19 + out@rootw + b); GRU -> h,out ----------------
__global__ void k_node(const float* __restrict__ nn2b, const float* __restrict__ rootw,
                       const float* __restrict__ convb,
                       const float* __restrict__ wih, const float* __restrict__ whh,
                       const float* __restrict__ bih, const float* __restrict__ bhh) {
    __shared__ float sx_s[4][64], out_s[4][64], h_s[4][64], m_s[4][64];
    __shared__ float g1[4][128], g2[4][64], g3[4][64];
    int t = threadIdx.x;
    int ln = t >> 6, o = t & 63;
    int n = blockIdx.x * 4 + ln;

    sx_s[ln][o]  = g_Sx[n * 64 + o];
    out_s[ln][o] = g_out[n * 64 + o];
    h_s[ln][o]   = g_h[n * 64 + o];
    __syncthreads();

    {
        float s = 0.0f;
#pragma unroll
        for (int q = 0; q < KSPLIT; q++) s += g_part[(size_t)q * (NNODES * DIM) + n * 64 + o];
        float acc = 0.0f;
#pragma unroll
        for (int i = 0; i < 64; i++) {
            s   = fmaf(sx_s[ln][i],  nn2b[i * 64 + o], s);
            acc = fmaf(out_s[ln][i], rootw[i * 64 + o], acc);
        }
        m_s[ln][o] = fmaxf(s * (1.0f / 19.0f) + acc + convb[o], 0.0f);
    }
    __syncthreads();

#pragma unroll
    for (int q = 0; q < 3; q++) {
        int j = o + q * 64;
        const float4* wi = (const float4*)(wih + j * 64);
        const float4* wh = (const float4*)(whh + j * 64);
        const float4* mr = (const float4*)(m_s[ln]);
        const float4* hr = (const float4*)(h_s[ln]);
        float gi = bih[j], gh = bhh[j];
#pragma unroll
        for (int qq = 0; qq < 16; qq++) {
            float4 a = mr[qq], b = wi[qq];
            gi = fmaf(a.x, b.x, fmaf(a.y, b.y, fmaf(a.z, b.z, fmaf(a.w, b.w, gi))));
            float4 c = hr[qq], d = wh[qq];
            gh = fmaf(c.x, d.x, fmaf(c.y, d.y, fmaf(c.z, d.z, fmaf(c.w, d.w, gh))));
        }
        if (q < 2) g1[ln][j] = gi + gh;
        else { g2[ln][o] = gi; g3[ln][o] = gh; }
    }
    __syncthreads();

    {
        float r  = sigf(g1[ln][o]);
        float z  = sigf(g1[ln][64 + o]);
        float nn = tanhf(g2[ln][o] + r * g3[ln][o]);
        float h  = (1.0f - z) * nn + z * h_s[ln][o];
        g_h[n * 64 + o]   = h;
        g_out[n * 64 + o] = h;
    }
}

// ---------------- Set2Set (3 steps) + final MLP head, one block per graph ----------------
__global__ void k_s2s(const float* __restrict__ wih, const float* __restrict__ whh,
                      const float* __restrict__ bih, const float* __restrict__ bhh,
                      const float* __restrict__ l1w, const float* __restrict__ l1b,
                      const float* __restrict__ l2w, const float* __restrict__ l2b,
                      float* __restrict__ outp) {
    __shared__ float og[NPER * 64];
    __shared__ float qs[128], hl[64], cl[64], gates[256], ev[NPER], av[NPER], red[64];
    __shared__ float ssum;
    int g = blockIdx.x, t = threadIdx.x;               // 128 threads

    for (int u = t; u < NPER * 64; u += 128) og[u] = g_out[g * NPER * 64 + u];
    qs[t] = 0.0f;
    if (t < 64) { hl[t] = 0.0f; cl[t] = 0.0f; }
    __syncthreads();

    for (int step = 0; step < 3; step++) {
        for (int j = t; j < 256; j += 128) {
            float acc = bih[j] + bhh[j];
            const float* wr = wih + j * 128;
            for (int i = 0; i < 128; i++) acc = fmaf(qs[i], wr[i], acc);
            const float* w2 = whh + j * 64;
            for (int i = 0; i < 64; i++) acc = fmaf(hl[i], w2[i], acc);
            gates[j] = acc;
        }
        __syncthreads();
        if (t < 64) {
            float ig = gates[t], fg = gates[64 + t], gg = gates[128 + t], og_ = gates[192 + t];
            float c = sigf(fg) * cl[t] + sigf(ig) * tanhf(gg);
            cl[t] = c;
            hl[t] = sigf(og_) * tanhf(c);
        }
        __syncthreads();
        if (t < NPER) {
            float acc = 0.0f;
            for (int o = 0; o < 64; o++) acc = fmaf(og[t * 64 + o], hl[o], acc);
            ev[t] = acc;
        }
        __syncthreads();
        if (t == 0) {
            float mx = ev[0];
            for (int v = 1; v < NPER; v++) mx = fmaxf(mx, ev[v]);
            float s = 0.0f;
            for (int v = 0; v < NPER; v++) { av[v] = expf(ev[v] - mx); s += av[v]; }
            ssum = s;
        }
        __syncthreads();
        if (t < 64) {
            float acc = 0.0f;
            for (int v = 0; v < NPER; v++) acc = fmaf(av[v], og[v * 64 + t], acc);
            qs[t] = hl[t];
            qs[64 + t] = acc / ssum;
        }
        __syncthreads();
    }

    if (t < 64) {
        float acc = l1b[t];
        for (int i = 0; i < 128; i++) acc = fmaf(qs[i], l1w[i * 64 + t], acc);
        acc = fmaxf(acc, 0.0f);
        red[t] = acc * l2w[t];
    }
    __syncthreads();
    if (t == 0) {
        float y = l2b[0];
        for (int o = 0; o < 64; o++) y += red[o];
        outp[g] = y;
    }
}

// ---------------- host launch ----------------
extern "C" void kernel_launch(void* const* d_in, const int* in_sizes, int n_in,
                              void* d_out, int out_size) {
    const float* x       = (const float*)d_in[0];
    const float* ea      = (const float*)d_in[2];
    const float* lin0_w  = (const float*)d_in[4];
    const float* lin0_b  = (const float*)d_in[5];
    const float* nn1_w   = (const float*)d_in[6];
    const float* nn1_b   = (const float*)d_in[7];
    const float* nn2_w   = (const float*)d_in[8];
    const float* nn2_b   = (const float*)d_in[9];
    const float* root_w  = (const float*)d_in[10];
    const float* conv_b  = (const float*)d_in[11];
    const float* gru_wih = (const float*)d_in[12];
    const float* gru_whh = (const float*)d_in[13];
    const float* gru_bih = (const float*)d_in[14];
    const float* gru_bhh = (const float*)d_in[15];
    const float* lstm_wih = (const float*)d_in[16];
    const float* lstm_whh = (const float*)d_in[17];
    const float* lstm_bih = (const float*)d_in[18];
    const float* lstm_bhh = (const float*)d_in[19];
    const float* lin1_w  = (const float*)d_in[20];
    const float* lin1_b  = (const float*)d_in[21];
    const float* lin2_w  = (const float*)d_in[22];
    const float* lin2_b  = (const float*)d_in[23];
    float* outp = (float*)d_out;

    k_lin0<<<(NNODES * DIM + 255) / 256, 256>>>(x, lin0_w, lin0_b);
    k_edge<<<(NEDGE * H1DIM) / 256, 256>>>(ea, nn1_w, nn1_b);

    for (int it = 0; it < 3; it++) {
        k_p<<<NNODES, 256>>>();
        k_agg<<<640, 128>>>(nn2_w);
        k_node<<<NNODES / 4, 256>>>(nn2_b, root_w, conv_b,
                                    gru_wih, gru_whh, gru_bih, gru_bhh);
    }

    k_s2s<<<NGRAPH, 128>>>(lstm_wih, lstm_whh, lstm_bih, lstm_bhh,
                           lin1_w, lin1_b, lin2_w, lin2_b, outp);
}

// round 11
// speedup vs baseline: 1.7572x; 1.2529x over previous
#include <cuda_runtime.h>
#include <cuda_bf16.h>
#include <math.h>
#include <stdint.h>

// ---------------- problem constants ----------------
#define NGRAPH 128
#define NPER   20
#define NNODES 2560          // 128*20
#define EPG    380           // 20*19
#define NEDGE  48640         // 128*380
#define DIM    64
#define H1DIM  128
#define KK     8192          // H1DIM*DIM
#define KSPLIT 32            // k_agg K-splits (each CTA covers 256 k)

// ---------------- packed f32x2 helpers (sm_100+) ----------------
#define FMA2(acc, a, b) asm("fma.rn.f32x2 %0, %1, %2, %0;" : "+l"(acc) : "l"(a), "l"(b))
#define PACK2(out, f)   asm("mov.b64 %0, {%1, %1};" : "=l"(out) : "f"(f))
#define PACK2U(out, u)  asm("mov.b64 %0, {%1, %1};" : "=l"(out) : "r"(u))
#define PACK2UU(out, a, b) asm("mov.b64 %0, {%1, %2};" : "=l"(out) : "r"(a), "r"(b))
#define UNPK2(lo, hi, p) asm("mov.b64 {%0, %1}, %2;" : "=f"(lo), "=f"(hi) : "l"(p))
#define CVTB2(out, lo, hi) asm("cvt.rn.bf16x2.f32 %0, %1, %2;" : "=r"(out) : "f"(hi), "f"(lo))

// ---------------- scratch (static device globals; no allocation) ----------------
__device__ unsigned short g_h1b[NEDGE * H1DIM];   // 12.5 MB bf16 edge MLP hidden
__device__ unsigned short g_Pb[NNODES * KK];      // 42 MB bf16 outer-product accumulators
__device__ float g_part[KSPLIT * NNODES * DIM];   // 21 MB split-K partials
__device__ float g_Sx[NNODES * DIM];
__device__ float g_out[NNODES * DIM];
__device__ float g_h  [NNODES * DIM];
__device__ float g_wihT[64 * 192];                // GRU weights transposed [i][j]
__device__ float g_whhT[64 * 192];

__device__ __forceinline__ float sigf(float x) { return 1.0f / (1.0f + expf(-x)); }

// ---------------- out = relu(x @ lin0_w + b); h = out ----------------
__global__ void k_lin0(const float* __restrict__ x, const float* __restrict__ w,
                       const float* __restrict__ b) {
    int idx = blockIdx.x * 256 + threadIdx.x;
    if (idx >= NNODES * DIM) return;
    int n = idx >> 6, o = idx & 63;
    const float* xr = x + n * 11;
    float acc = b[o];
#pragma unroll
    for (int f = 0; f < 11; f++) acc = fmaf(xr[f], w[f * 64 + o], acc);
    acc = fmaxf(acc, 0.0f);
    g_out[idx] = acc;
    g_h[idx]   = acc;
}

// ---------------- h1 = relu(edge_attr @ nn1_w + nn1_b) -> bf16 ----------------
__global__ void k_edge(const float* __restrict__ ea, const float* __restrict__ w,
                       const float* __restrict__ b) {
    int idx = blockIdx.x * 256 + threadIdx.x;
    if (idx >= NEDGE * H1DIM) return;
    int e = idx >> 7, k = idx & 127;
    const float* er = ea + e * 5;
    float acc = b[k];
#pragma unroll
    for (int f = 0; f < 5; f++) acc = fmaf(er[f], w[f * 128 + k], acc);
    acc = fmaxf(acc, 0.0f);
    g_h1b[idx] = __bfloat16_as_ushort(__float2bfloat16(acc));
}

// ---------------- transpose GRU weights (once); also shifts ncu capture slot ----------------
__global__ void k_prepw(const float* __restrict__ wih, const float* __restrict__ whh) {
    int idx = blockIdx.x * 256 + threadIdx.x;
    if (idx >= 64 * 192) return;
    int i = idx / 192, j = idx % 192;
    g_wihT[idx] = wih[j * 64 + i];
    g_whhT[idx] = whh[j * 64 + i];
}

// ---------------- P[d] = sum_s h1[s->d] (outer) out[s] -> bf16; also Sx[d] ----------------
__global__ void k_p() {
    __shared__ float xs[19 * 64];
    __shared__ unsigned hsu[19 * 64];   // bf16 pairs (2 k per u32)
    int n = blockIdx.x;
    int g = n / NPER, d = n % NPER;
    int t = threadIdx.x;                // 256 threads

    for (int u = t; u < 19 * 64; u += 256) {
        int sI = u >> 6, i = u & 63;
        int s = sI + (sI >= d);
        xs[u] = g_out[(g * NPER + s) * 64 + i];
    }
    for (int u = t; u < 19 * 64; u += 256) {
        int sI = u >> 6, kp = u & 63;
        int s = sI + (sI >= d);
        int j = (d < s) ? d : d - 1;
        hsu[u] = ((const unsigned*)g_h1b)[(size_t)(g * EPG + s * 19 + j) * 64 + kp];
    }
    __syncthreads();

    if (t < 64) {
        float acc = 0.0f;
#pragma unroll
        for (int sI = 0; sI < 19; sI++) acc += xs[sI * 64 + t];
        g_Sx[n * 64 + t] = acc;
    }

    int kg = t >> 3, ig = t & 7;        // 4 k-rows x 8 i-cols per thread
    unsigned long long a2[4][4];
#pragma unroll
    for (int r = 0; r < 4; r++)
#pragma unroll
        for (int c = 0; c < 4; c++) a2[r][c] = 0ULL;

    for (int sI = 0; sI < 19; sI++) {
        uint2 hh = *(const uint2*)(hsu + sI * 64 + (kg << 1));
        float f0 = __uint_as_float(hh.x << 16);
        float f1 = __uint_as_float(hh.x & 0xFFFF0000u);
        float f2 = __uint_as_float(hh.y << 16);
        float f3 = __uint_as_float(hh.y & 0xFFFF0000u);
        ulonglong2 xa = *(const ulonglong2*)(xs + sI * 64 + (ig << 3));
        ulonglong2 xb = *(const ulonglong2*)(xs + sI * 64 + (ig << 3) + 4);
        unsigned long long h0, h1p, h2, h3;
        PACK2(h0, f0); PACK2(h1p, f1); PACK2(h2, f2); PACK2(h3, f3);
        FMA2(a2[0][0], h0, xa.x);  FMA2(a2[0][1], h0, xa.y);
        FMA2(a2[0][2], h0, xb.x);  FMA2(a2[0][3], h0, xb.y);
        FMA2(a2[1][0], h1p, xa.x); FMA2(a2[1][1], h1p, xa.y);
        FMA2(a2[1][2], h1p, xb.x); FMA2(a2[1][3], h1p, xb.y);
        FMA2(a2[2][0], h2, xa.x);  FMA2(a2[2][1], h2, xa.y);
        FMA2(a2[2][2], h2, xb.x);  FMA2(a2[2][3], h2, xb.y);
        FMA2(a2[3][0], h3, xa.x);  FMA2(a2[3][1], h3, xa.y);
        FMA2(a2[3][2], h3, xb.x);  FMA2(a2[3][3], h3, xb.y);
    }

    unsigned short* pd = g_Pb + (size_t)n * KK;
#pragma unroll
    for (int r = 0; r < 4; r++) {
        int k = (kg << 2) + r;
        unsigned o0, o1, o2, o3;
        float lo, hi;
        UNPK2(lo, hi, a2[r][0]); CVTB2(o0, lo, hi);
        UNPK2(lo, hi, a2[r][1]); CVTB2(o1, lo, hi);
        UNPK2(lo, hi, a2[r][2]); CVTB2(o2, lo, hi);
        UNPK2(lo, hi, a2[r][3]); CVTB2(o3, lo, hi);
        *(uint4*)(pd + k * 64 + (ig << 3)) = make_uint4(o0, o1, o2, o3);
    }
}

// ---------------- k_agg: partial[ks] = Pb[128-row tile] @ T over 256-k slice ----------------
__global__ void __launch_bounds__(128, 4) k_agg(const float* __restrict__ nn2w) {
    __shared__ unsigned Tsu[32 * 32];   // 4 KB: [k][col-pair] bf16x2
    int bx = blockIdx.x;
    int tile = bx >> 5, ks = bx & 31;
    int n0 = tile * 128;
    int kbase = ks * 256;
    int t = threadIdx.x;
    int tx = t & 7, ry = t >> 3;        // cols tx*8..+7, rows ry*8..+7
    int r0 = n0 + (ry << 3);

    unsigned long long acc[8][4];       // [row][col-pair] f32x2 {col even, col odd}
#pragma unroll
    for (int r = 0; r < 8; r++)
#pragma unroll
        for (int c = 0; c < 4; c++) acc[r][c] = 0ULL;

    for (int ch = 0; ch < 8; ch++) {
        int kb = kbase + (ch << 5);
        if (ch) __syncthreads();
#pragma unroll
        for (int j = 0; j < 4; j++) {
            int flat = t + j * 128;     // 0..511
            int kk = flat >> 4, o4 = (flat & 15) << 2;
            float4 v = *(const float4*)(nn2w + (size_t)(kb + kk) * 64 + o4);
            unsigned u0, u1;
            CVTB2(u0, v.x, v.y);
            CVTB2(u1, v.z, v.w);
            *(uint2*)(Tsu + (kk << 5) + (o4 >> 1)) = make_uint2(u0, u1);
        }
        __syncthreads();
#pragma unroll
        for (int kq = 0; kq < 4; kq++) {
            uint4 q[8];
#pragma unroll
            for (int r = 0; r < 8; r++)
                q[r] = *(const uint4*)(g_Pb + (size_t)(r0 + r) * KK + kb + (kq << 3));
#pragma unroll
            for (int kk = 0; kk < 8; kk++) {
                uint4 tw = *(const uint4*)(Tsu + (((kq << 3) + kk) << 5) + (tx << 2));
                unsigned long long tp0, tp1, tp2, tp3;
                PACK2UU(tp0, tw.x << 16, tw.x & 0xFFFF0000u);
                PACK2UU(tp1, tw.y << 16, tw.y & 0xFFFF0000u);
                PACK2UU(tp2, tw.z << 16, tw.z & 0xFFFF0000u);
                PACK2UU(tp3, tw.w << 16, tw.w & 0xFFFF0000u);
#pragma unroll
                for (int r = 0; r < 8; r++) {
                    unsigned w = ((const unsigned*)&q[r])[kk >> 1];
                    unsigned f = (kk & 1) ? (w & 0xFFFF0000u) : (w << 16);
                    unsigned long long pd;
                    PACK2U(pd, f);
                    FMA2(acc[r][0], pd, tp0);
                    FMA2(acc[r][1], pd, tp1);
                    FMA2(acc[r][2], pd, tp2);
                    FMA2(acc[r][3], pd, tp3);
                }
            }
        }
    }

    float* gp = g_part + (size_t)ks * (NNODES * DIM) + (size_t)r0 * 64 + (tx << 3);
#pragma unroll
    for (int r = 0; r < 8; r++) {
        ulonglong2 v0, v1;
        v0.x = acc[r][0]; v0.y = acc[r][1];
        v1.x = acc[r][2]; v1.y = acc[r][3];
        *(ulonglong2*)(gp + (size_t)r * 64)     = v0;
        *(ulonglong2*)(gp + (size_t)r * 64 + 4) = v1;
    }
}

// ---------------- fused per-node: m = relu(agg/19 + out@rootw + b); GRU -> h,out ----------------
// gates use TRANSPOSED weights: lane-consecutive (coalesced) loads, 1 wf per load
__global__ void k_node(const float* __restrict__ nn2b, const float* __restrict__ rootw,
                       const float* __restrict__ convb,
                       const float* __restrict__ bih, const float* __restrict__ bhh) {
    __shared__ float sx_s[4][64], out_s[4][64], h_s[4][64], m_s[4][64];
    int t = threadIdx.x;
    int ln = t >> 6, o = t & 63;
    int n = blockIdx.x * 4 + ln;

    sx_s[ln][o]  = g_Sx[n * 64 + o];
    out_s[ln][o] = g_out[n * 64 + o];
    h_s[ln][o]   = g_h[n * 64 + o];
    __syncthreads();

    {
        float s = 0.0f;
#pragma unroll
        for (int q = 0; q < KSPLIT; q++) s += g_part[(size_t)q * (NNODES * DIM) + n * 64 + o];
        float acc = 0.0f;
#pragma unroll
        for (int i = 0; i < 64; i++) {
            s   = fmaf(sx_s[ln][i],  nn2b[i * 64 + o], s);
            acc = fmaf(out_s[ln][i], rootw[i * 64 + o], acc);
        }
        m_s[ln][o] = fmaxf(s * (1.0f / 19.0f) + acc + convb[o], 0.0f);
    }
    __syncthreads();

    {
        float gi0 = bih[o], gi1 = bih[o + 64], gi2 = bih[o + 128];
        float gh0 = bhh[o], gh1 = bhh[o + 64], gh2 = bhh[o + 128];
#pragma unroll 8
        for (int i = 0; i < 64; i++) {
            float mi = m_s[ln][i], hi = h_s[ln][i];
            const float* wiT = g_wihT + i * 192 + o;
            const float* whT = g_whhT + i * 192 + o;
            gi0 = fmaf(mi, wiT[0],   gi0);
            gi1 = fmaf(mi, wiT[64],  gi1);
            gi2 = fmaf(mi, wiT[128], gi2);
            gh0 = fmaf(hi, whT[0],   gh0);
            gh1 = fmaf(hi, whT[64],  gh1);
            gh2 = fmaf(hi, whT[128], gh2);
        }
        float r  = sigf(gi0 + gh0);
        float z  = sigf(gi1 + gh1);
        float nn = tanhf(gi2 + r * gh2);
        float h  = (1.0f - z) * nn + z * h_s[ln][o];
        g_h[n * 64 + o]   = h;
        g_out[n * 64 + o] = h;
    }
}

// ---------------- Set2Set (3 steps) + final MLP head, one block per graph ----------------
__global__ void k_s2s(const float* __restrict__ wih, const float* __restrict__ whh,
                      const float* __restrict__ bih, const float* __restrict__ bhh,
                      const float* __restrict__ l1w, const float* __restrict__ l1b,
                      const float* __restrict__ l2w, const float* __restrict__ l2b,
                      float* __restrict__ outp) {
    __shared__ float og[NPER * 64];
    __shared__ float qs[128], hl[64], cl[64], gates[256], ev[NPER], av[NPER], red[64];
    __shared__ float ssum;
    int g = blockIdx.x, t = threadIdx.x;               // 128 threads

    for (int u = t; u < NPER * 64; u += 128) og[u] = g_out[g * NPER * 64 + u];
    qs[t] = 0.0f;
    if (t < 64) { hl[t] = 0.0f; cl[t] = 0.0f; }
    __syncthreads();

    for (int step = 0; step < 3; step++) {
        for (int j = t; j < 256; j += 128) {
            float acc = bih[j] + bhh[j];
            const float* wr = wih + j * 128;
            for (int i = 0; i < 128; i++) acc = fmaf(qs[i], wr[i], acc);
            const float* w2 = whh + j * 64;
            for (int i = 0; i < 64; i++) acc = fmaf(hl[i], w2[i], acc);
            gates[j] = acc;
        }
        __syncthreads();
        if (t < 64) {
            float ig = gates[t], fg = gates[64 + t], gg = gates[128 + t], og_ = gates[192 + t];
            float c = sigf(fg) * cl[t] + sigf(ig) * tanhf(gg);
            cl[t] = c;
            hl[t] = sigf(og_) * tanhf(c);
        }
        __syncthreads();
        if (t < NPER) {
            float acc = 0.0f;
            for (int o = 0; o < 64; o++) acc = fmaf(og[t * 64 + o], hl[o], acc);
            ev[t] = acc;
        }
        __syncthreads();
        if (t == 0) {
            float mx = ev[0];
            for (int v = 1; v < NPER; v++) mx = fmaxf(mx, ev[v]);
            float s = 0.0f;
            for (int v = 0; v < NPER; v++) { av[v] = expf(ev[v] - mx); s += av[v]; }
            ssum = s;
        }
        __syncthreads();
        if (t < 64) {
            float acc = 0.0f;
            for (int v = 0; v < NPER; v++) acc = fmaf(av[v], og[v * 64 + t], acc);
            qs[t] = hl[t];
            qs[64 + t] = acc / ssum;
        }
        __syncthreads();
    }

    if (t < 64) {
        float acc = l1b[t];
        for (int i = 0; i < 128; i++) acc = fmaf(qs[i], l1w[i * 64 + t], acc);
        acc = fmaxf(acc, 0.0f);
        red[t] = acc * l2w[t];
    }
    __syncthreads();
    if (t == 0) {
        float y = l2b[0];
        for (int o = 0; o < 64; o++) y += red[o];
        outp[g] = y;
    }
}

// ---------------- host launch ----------------
extern "C" void kernel_launch(void* const* d_in, const int* in_sizes, int n_in,
                              void* d_out, int out_size) {
    const float* x       = (const float*)d_in[0];
    const float* ea      = (const float*)d_in[2];
    const float* lin0_w  = (const float*)d_in[4];
    const float* lin0_b  = (const float*)d_in[5];
    const float* nn1_w   = (const float*)d_in[6];
    const float* nn1_b   = (const float*)d_in[7];
    const float* nn2_w   = (const float*)d_in[8];
    const float* nn2_b   = (const float*)d_in[9];
    const float* root_w  = (const float*)d_in[10];
    const float* conv_b  = (const float*)d_in[11];
    const float* gru_wih = (const float*)d_in[12];
    const float* gru_whh = (const float*)d_in[13];
    const float* gru_bih = (const float*)d_in[14];
    const float* gru_bhh = (const float*)d_in[15];
    const float* lstm_wih = (const float*)d_in[16];
    const float* lstm_whh = (const float*)d_in[17];
    const float* lstm_bih = (const float*)d_in[18];
    const float* lstm_bhh = (const float*)d_in[19];
    const float* lin1_w  = (const float*)d_in[20];
    const float* lin1_b  = (const float*)d_in[21];
    const float* lin2_w  = (const float*)d_in[22];
    const float* lin2_b  = (const float*)d_in[23];
    float* outp = (float*)d_out;

    k_lin0<<<(NNODES * DIM + 255) / 256, 256>>>(x, lin0_w, lin0_b);
    k_edge<<<(NEDGE * H1DIM) / 256, 256>>>(ea, nn1_w, nn1_b);
    k_prepw<<<(64 * 192 + 255) / 256, 256>>>(gru_wih, gru_whh);

    for (int it = 0; it < 3; it++) {
        k_p<<<NNODES, 256>>>();
        k_agg<<<640, 128>>>(nn2_w);
        k_node<<<NNODES / 4, 256>>>(nn2_b, root_w, conv_b, gru_bih, gru_bhh);
    }

    k_s2s<<<NGRAPH, 128>>>(lstm_wih, lstm_whh, lstm_bih, lstm_bhh,
                           lin1_w, lin1_b, lin2_w, lin2_b, outp);
}